// round 11
// baseline (speedup 1.0000x reference)
#include <cuda_runtime.h>

#define NN 100000
#define NE 3200000
#define CAP 128          // fixed bucket capacity per dst node (max deg ~70 incl self-loop)
#define SMAX 128
#define NW 8             // warps per edge-kernel block

// ---------------- scratch (device globals; no allocs allowed) ----------------
__device__ __align__(128) int    g_cnt[NN];         // cursor: init 1 (self-loop at slot 0)
__device__ __align__(128) int    g_csr[NN * CAP];   // bucketed adjacency: src ids
__device__ __align__(128) float  g_h[NN * 32];      // node features fp32 (stride = CH of layer)
__device__ __align__(128) float  g_o[NN * 32];      // aggregated out (fp32)
__device__ __align__(128) float4 g_ea[NN];          // src-side: (exp(als0), exp(.2als0), exp(als1), exp(.2als1))
__device__ __align__(128) float4 g_eb[NN];          // dst-side: (exp(ald0), exp(.2ald0), exp(ald1), exp(.2ald1))

// ---------------- single-pass bucketed scatter ----------------
__global__ void k_scatter(const int4* __restrict__ src4, const int4* __restrict__ dst4) {
    int e = blockIdx.x * blockDim.x + threadIdx.x;
    if (e >= NE / 4) return;
    int4 s = src4[e];
    int4 d = dst4[e];
    int p;
    p = atomicAdd(&g_cnt[d.x], 1); if (p < CAP) g_csr[d.x * CAP + p] = s.x;
    p = atomicAdd(&g_cnt[d.y], 1); if (p < CAP) g_csr[d.y * CAP + p] = s.y;
    p = atomicAdd(&g_cnt[d.z], 1); if (p < CAP) g_csr[d.z * CAP + p] = s.z;
    p = atomicAdd(&g_cnt[d.w], 1); if (p < CAP) g_csr[d.w * CAP + p] = s.w;
}

// ---------------- layer 1 node transform (seeds cursor + self-loop slot) ------
__global__ void k_node1(const float* __restrict__ x, const float* __restrict__ W,
                        const float* __restrict__ as_, const float* __restrict__ ad_) {
    int n = blockIdx.x * blockDim.x + threadIdx.x;
    if (n >= NN) return;
    g_cnt[n] = 1;                 // cursor starts after self-loop
    g_csr[n * CAP] = n;           // self-loop at slot 0
    float x0 = x[n * 3 + 0], x1 = x[n * 3 + 1], x2 = x[n * 3 + 2];
    float als0 = 0.f, als1 = 0.f, ald0 = 0.f, ald1 = 0.f;
#pragma unroll
    for (int j = 0; j < 8; j++) {
        float q[4];
#pragma unroll
        for (int u = 0; u < 4; u++) {
            int c = 4 * j + u;
            float h = fmaf(x0, __ldg(&W[c]), fmaf(x1, __ldg(&W[32 + c]), x2 * __ldg(&W[64 + c])));
            q[u] = h;
            float vs = h * __ldg(&as_[c]), vd = h * __ldg(&ad_[c]);
            if (c < 16) { als0 += vs; ald0 += vd; }
            else        { als1 += vs; ald1 += vd; }
        }
        ((float4*)g_h)[n * 8 + j] = make_float4(q[0], q[1], q[2], q[3]);
    }
    g_ea[n] = make_float4(__expf(als0), __expf(0.2f * als0), __expf(als1), __expf(0.2f * als1));
    g_eb[n] = make_float4(__expf(ald0), __expf(0.2f * ald0), __expf(ald1), __expf(0.2f * ald1));
}

// ---------------- edge aggregation, H=2 CH=32: one warp per dst ----------------
// weight(edge) = exp(leaky_relu(a+b,0.2)) = (E1s*B1w >= 1) ? E1s*B1w : E5s*B5w
__global__ void __launch_bounds__(256) k_edge2() {
    __shared__ int   s_s[NW][SMAX];
    __shared__ float s_a[NW][SMAX * 2];   // [jj][h] interleaved
    int widx = threadIdx.x >> 5;
    int lane = threadIdx.x & 31;
    int w = blockIdx.x * NW + widx;       // NN % NW == 0

    int start = w * CAP;
    int deg   = min(g_cnt[w], CAP);       // deg <= CAP always in practice
    float4 B = g_eb[w];

    // phase A: factored softmax weight per edge (no exp), denominator, cache
    float ss0 = 0.f, ss1 = 0.f;
    for (int jj = lane; jj < deg; jj += 32) {
        int s = g_csr[start + jj];
        float4 E = g_ea[s];
        float t0 = E.x * B.x, u0 = E.y * B.y;
        float t1 = E.z * B.z, u1 = E.w * B.w;
        float w0 = (t0 >= 1.f) ? t0 : u0;
        float w1 = (t1 >= 1.f) ? t1 : u1;
        ss0 += w0; ss1 += w1;
        s_s[widx][jj] = s;
        ((float2*)s_a[widx])[jj] = make_float2(w0, w1);
    }
#pragma unroll
    for (int o = 16; o > 0; o >>= 1) {
        ss0 += __shfl_xor_sync(0xffffffffu, ss0, o);
        ss1 += __shfl_xor_sync(0xffffffffu, ss1, o);
    }
    __syncwarp();

    // phase C: 4 edge groups x 8 float4 channel-quads; LDG.128 per edge-slice
    const float4* h4 = (const float4*)g_h;
    int eg = lane >> 3;        // edge group 0..3
    int c4 = lane & 7;         // float4 index -> channels 4c4..4c4+3
    int hsel = c4 >> 2;        // head of this quad
    float ax = 0.f, ay = 0.f, az = 0.f, aw = 0.f;
    int base = 0;
    for (; base + 8 <= deg; base += 8) {
        int e0 = base + eg, e1 = base + 4 + eg;
        int s0 = s_s[widx][e0], s1 = s_s[widx][e1];
        float a0 = s_a[widx][e0 * 2 + hsel];
        float a1 = s_a[widx][e1 * 2 + hsel];
        float4 f0 = h4[s0 * 8 + c4];
        float4 f1 = h4[s1 * 8 + c4];
        ax = fmaf(a0, f0.x, ax); ay = fmaf(a0, f0.y, ay);
        az = fmaf(a0, f0.z, az); aw = fmaf(a0, f0.w, aw);
        ax = fmaf(a1, f1.x, ax); ay = fmaf(a1, f1.y, ay);
        az = fmaf(a1, f1.z, az); aw = fmaf(a1, f1.w, aw);
    }
#pragma unroll 1
    for (int e = base + eg; e < deg; e += 4) {
        int s = s_s[widx][e];
        float a = s_a[widx][e * 2 + hsel];
        float4 f = h4[s * 8 + c4];
        ax = fmaf(a, f.x, ax); ay = fmaf(a, f.y, ay);
        az = fmaf(a, f.z, az); aw = fmaf(a, f.w, aw);
    }
    // reduce across the 4 edge groups (lane bits 3,4)
#pragma unroll
    for (int o = 8; o <= 16; o <<= 1) {
        ax += __shfl_xor_sync(0xffffffffu, ax, o);
        ay += __shfl_xor_sync(0xffffffffu, ay, o);
        az += __shfl_xor_sync(0xffffffffu, az, o);
        aw += __shfl_xor_sync(0xffffffffu, aw, o);
    }
    float inv = 1.f / ((hsel ? ss1 : ss0) + 1e-16f);
    if (eg == 0)
        ((float4*)g_o)[w * 8 + c4] = make_float4(ax * inv, ay * inv, az * inv, aw * inv);
}

// ---------------- layer 3 edges (H=1, CH=8) fused with output head ----------------
__global__ void __launch_bounds__(256) k_edge1_final(
        const float* __restrict__ b3, const float* __restrict__ Wo,
        const float* __restrict__ bo, float* __restrict__ out) {
    __shared__ int   s_s[NW][SMAX];
    __shared__ float s_a[NW][SMAX];
    int widx = threadIdx.x >> 5;
    int lane = threadIdx.x & 31;
    int w = blockIdx.x * NW + widx;

    int start = w * CAP;
    int deg   = min(g_cnt[w], CAP);
    float4 B = g_eb[w];

    float ss = 0.f;
    for (int jj = lane; jj < deg; jj += 32) {
        int s = g_csr[start + jj];
        float4 E = g_ea[s];
        float t = E.x * B.x, u = E.y * B.y;
        float wgt = (t >= 1.f) ? t : u;
        ss += wgt;
        s_s[widx][jj] = s; s_a[widx][jj] = wgt;
    }
#pragma unroll
    for (int o = 16; o > 0; o >>= 1) ss += __shfl_xor_sync(0xffffffffu, ss, o);
    __syncwarp();
    float inv = 1.f / (ss + 1e-16f);

    // phase C: 16 edge groups x 2 float4 channel-quads (CH=8 -> 2 x float4 per node)
    const float4* h4 = (const float4*)g_h;
    int eg = lane >> 1;        // 0..15
    int c4 = lane & 1;         // 0..1 -> channels 4c4..4c4+3
    float ax = 0.f, ay = 0.f, az = 0.f, aw = 0.f;
    for (int e = eg; e < deg; e += 16) {
        float a = s_a[widx][e];
        float4 f = h4[s_s[widx][e] * 2 + c4];
        ax = fmaf(a, f.x, ax); ay = fmaf(a, f.y, ay);
        az = fmaf(a, f.z, az); aw = fmaf(a, f.w, aw);
    }
    // reduce over the 16 edge groups (lane bits 1..4)
#pragma unroll
    for (int o = 2; o <= 16; o <<= 1) {
        ax += __shfl_xor_sync(0xffffffffu, ax, o);
        ay += __shfl_xor_sync(0xffffffffu, ay, o);
        az += __shfl_xor_sync(0xffffffffu, az, o);
        aw += __shfl_xor_sync(0xffffffffu, aw, o);
    }

    // fused head on lanes 0 (ch 0-3) and 1 (ch 4-7): y = elu(out3+b3) @ Wo + bo
    float z0 = ax * inv + __ldg(&b3[4 * c4 + 0]);
    float z1 = ay * inv + __ldg(&b3[4 * c4 + 1]);
    float z2 = az * inv + __ldg(&b3[4 * c4 + 2]);
    float z3 = aw * inv + __ldg(&b3[4 * c4 + 3]);
    z0 = z0 > 0.f ? z0 : expm1f(z0);
    z1 = z1 > 0.f ? z1 : expm1f(z1);
    z2 = z2 > 0.f ? z2 : expm1f(z2);
    z3 = z3 > 0.f ? z3 : expm1f(z3);
    float p = fmaf(z0, __ldg(&Wo[4 * c4 + 0]),
             fmaf(z1, __ldg(&Wo[4 * c4 + 1]),
             fmaf(z2, __ldg(&Wo[4 * c4 + 2]), z3 * __ldg(&Wo[4 * c4 + 3]))));
    p += __shfl_xor_sync(0xffffffffu, p, 1);
    if (lane == 0) out[w] = p + __ldg(&bo[0]);
}

// ---------------- mid node transform (quad-wise, low reg pressure) ----------------
template <int CIN, int COUT, int H>
__global__ void __launch_bounds__(256) k_mid(
        const float* __restrict__ b, const float* __restrict__ W,
        const float* __restrict__ as_, const float* __restrict__ ad_) {
    __shared__ float sW[CIN * COUT];
    __shared__ float sb[CIN];
    __shared__ float sas[COUT], sad[COUT];
    for (int i = threadIdx.x; i < CIN * COUT; i += blockDim.x) sW[i] = W[i];
    for (int i = threadIdx.x; i < CIN; i += blockDim.x) sb[i] = b[i];
    for (int i = threadIdx.x; i < COUT; i += blockDim.x) { sas[i] = as_[i]; sad[i] = ad_[i]; }
    __syncthreads();

    int n = blockIdx.x * blockDim.x + threadIdx.x;
    if (n >= NN) return;
    float z[CIN];
#pragma unroll
    for (int j = 0; j < CIN / 4; j++) {
        float4 v4 = ((const float4*)g_o)[n * (CIN / 4) + j];
        float v;
        v = v4.x + sb[4*j+0]; z[4*j+0] = v > 0.f ? v : expm1f(v);
        v = v4.y + sb[4*j+1]; z[4*j+1] = v > 0.f ? v : expm1f(v);
        v = v4.z + sb[4*j+2]; z[4*j+2] = v > 0.f ? v : expm1f(v);
        v = v4.w + sb[4*j+3]; z[4*j+3] = v > 0.f ? v : expm1f(v);
    }
    const int C = COUT / H;
    float als[H], ald[H];
#pragma unroll
    for (int h = 0; h < H; h++) { als[h] = 0.f; ald[h] = 0.f; }
    // quad-wise: 4 accumulators live at a time, store immediately
#pragma unroll
    for (int j = 0; j < COUT / 4; j++) {
        float a0 = 0.f, a1 = 0.f, a2 = 0.f, a3 = 0.f;
        int c0 = 4 * j;
#pragma unroll
        for (int i = 0; i < CIN; i++) {
            float zi = z[i];
            const float* wr = &sW[i * COUT + c0];
            a0 = fmaf(zi, wr[0], a0);
            a1 = fmaf(zi, wr[1], a1);
            a2 = fmaf(zi, wr[2], a2);
            a3 = fmaf(zi, wr[3], a3);
        }
        ((float4*)g_h)[n * (COUT / 4) + j] = make_float4(a0, a1, a2, a3);
        int h = c0 / C;   // quads never straddle heads
        als[h] = fmaf(a0, sas[c0+0], fmaf(a1, sas[c0+1], fmaf(a2, sas[c0+2], fmaf(a3, sas[c0+3], als[h]))));
        ald[h] = fmaf(a0, sad[c0+0], fmaf(a1, sad[c0+1], fmaf(a2, sad[c0+2], fmaf(a3, sad[c0+3], ald[h]))));
    }
    if (H == 2) {
        g_ea[n] = make_float4(__expf(als[0]), __expf(0.2f * als[0]),
                              __expf(als[1]), __expf(0.2f * als[1]));
        g_eb[n] = make_float4(__expf(ald[0]), __expf(0.2f * ald[0]),
                              __expf(ald[1]), __expf(0.2f * ald[1]));
    } else {
        float e1 = __expf(als[0]), e5 = __expf(0.2f * als[0]);
        g_ea[n] = make_float4(e1, e5, e1, e5);
        float f1 = __expf(ald[0]), f5 = __expf(0.2f * ald[0]);
        g_eb[n] = make_float4(f1, f5, f1, f5);
    }
}

// ---------------- launch ----------------
extern "C" void kernel_launch(void* const* d_in, const int* in_sizes, int n_in,
                              void* d_out, int out_size) {
    const float* x   = (const float*)d_in[0];
    const int*   ei  = (const int*)d_in[1];
    const float* W1  = (const float*)d_in[2];
    const float* as1 = (const float*)d_in[3];
    const float* ad1 = (const float*)d_in[4];
    const float* b1  = (const float*)d_in[5];
    const float* W2  = (const float*)d_in[6];
    const float* as2 = (const float*)d_in[7];
    const float* ad2 = (const float*)d_in[8];
    const float* b2  = (const float*)d_in[9];
    const float* W3  = (const float*)d_in[10];
    const float* as3 = (const float*)d_in[11];
    const float* ad3 = (const float*)d_in[12];
    const float* b3  = (const float*)d_in[13];
    const float* Wo  = (const float*)d_in[14];
    const float* bo  = (const float*)d_in[15];
    float* out = (float*)d_out;

    const int4* src4 = (const int4*)ei;            // edge_index[0]
    const int4* dst4 = (const int4*)(ei + NE);     // edge_index[1]

    // node transform first: seeds cursors (g_cnt=1) + self-loop slot 0
    k_node1<<<(NN + 255) / 256, 256>>>(x, W1, as1, ad1);
    // single-pass bucketed adjacency build
    k_scatter<<<(NE / 4 + 255) / 256, 256>>>(src4, dst4);

    const int EB = NN / NW;   // 12500 blocks, one warp per dst node
    // layer 1 edges (H=2, C=16)
    k_edge2<<<EB, 256>>>();
    // layer 2 (H=2, C=16)
    k_mid<32, 32, 2><<<(NN + 255) / 256, 256>>>(b1, W2, as2, ad2);
    k_edge2<<<EB, 256>>>();
    // layer 3 (H=1, C=8) + fused output head
    k_mid<32, 8, 1><<<(NN + 255) / 256, 256>>>(b2, W3, as3, ad3);
    k_edge1_final<<<EB, 256>>>(b3, Wo, bo, out);

    (void)in_sizes; (void)n_in; (void)out_size;
}

// round 12
// speedup vs baseline: 1.0511x; 1.0511x over previous
#include <cuda_runtime.h>

#define NN 100000
#define NE 3200000
#define CAP 128          // fixed bucket capacity per dst node (max deg ~70 incl self-loop)
#define SMAX 128
#define NW 8             // warps per edge-kernel block

// ---------------- scratch (device globals; no allocs allowed) ----------------
__device__ __align__(128) int   g_cnt[NN];          // cursor: init 1 (self-loop at slot 0)
__device__ __align__(128) int   g_csr[NN * CAP];    // bucketed adjacency: src ids
__device__ __align__(128) float g_h[NN * 32];       // node features fp32 (stride = CH of layer)
__device__ __align__(128) float g_o[NN * 32];       // aggregated out (fp32)
__device__ __align__(128) float g_als[NN * 2];      // per-node src-attention scalar [n][h]
__device__ __align__(128) float g_ald[NN * 2];      // per-node dst-attention scalar [n][h]

// ---------------- single-pass bucketed scatter ----------------
__global__ void k_scatter(const int4* __restrict__ src4, const int4* __restrict__ dst4) {
    int e = blockIdx.x * blockDim.x + threadIdx.x;
    if (e >= NE / 4) return;
    int4 s = src4[e];
    int4 d = dst4[e];
    int p;
    p = atomicAdd(&g_cnt[d.x], 1); if (p < CAP) g_csr[d.x * CAP + p] = s.x;
    p = atomicAdd(&g_cnt[d.y], 1); if (p < CAP) g_csr[d.y * CAP + p] = s.y;
    p = atomicAdd(&g_cnt[d.z], 1); if (p < CAP) g_csr[d.z * CAP + p] = s.z;
    p = atomicAdd(&g_cnt[d.w], 1); if (p < CAP) g_csr[d.w * CAP + p] = s.w;
}

// ---------------- layer 1 node transform (seeds cursor + self-loop slot) ------
__global__ void k_node1(const float* __restrict__ x, const float* __restrict__ W,
                        const float* __restrict__ as_, const float* __restrict__ ad_) {
    int n = blockIdx.x * blockDim.x + threadIdx.x;
    if (n >= NN) return;
    g_cnt[n] = 1;                 // cursor starts after self-loop
    g_csr[n * CAP] = n;           // self-loop at slot 0
    float x0 = x[n * 3 + 0], x1 = x[n * 3 + 1], x2 = x[n * 3 + 2];
    float als0 = 0.f, als1 = 0.f, ald0 = 0.f, ald1 = 0.f;
#pragma unroll
    for (int j = 0; j < 8; j++) {
        float q[4];
#pragma unroll
        for (int u = 0; u < 4; u++) {
            int c = 4 * j + u;
            float h = fmaf(x0, __ldg(&W[c]), fmaf(x1, __ldg(&W[32 + c]), x2 * __ldg(&W[64 + c])));
            q[u] = h;
            float vs = h * __ldg(&as_[c]), vd = h * __ldg(&ad_[c]);
            if (c < 16) { als0 += vs; ald0 += vd; }
            else        { als1 += vs; ald1 += vd; }
        }
        ((float4*)g_h)[n * 8 + j] = make_float4(q[0], q[1], q[2], q[3]);
    }
    g_als[n * 2 + 0] = als0; g_als[n * 2 + 1] = als1;
    g_ald[n * 2 + 0] = ald0; g_ald[n * 2 + 1] = ald1;
}

__device__ __forceinline__ float lrelu(float v) { return v > 0.f ? v : 0.2f * v; }

// ---------------- edge aggregation, H=2 CH=32: one warp per dst ----------------
__global__ void __launch_bounds__(256) k_edge2() {
    __shared__ int   s_s[NW][SMAX];
    __shared__ float s_a[NW][SMAX * 2];   // [jj][h] interleaved
    int widx = threadIdx.x >> 5;
    int lane = threadIdx.x & 31;
    int w = blockIdx.x * NW + widx;       // NN % NW == 0

    int start = w * CAP;
    int deg   = min(g_cnt[w], CAP);       // deg <= CAP always in practice
    float2 aldv = ((const float2*)g_ald)[w];

    // phase A: exp(logit) per edge, denominator, cache (src, e0, e1)
    float ss0 = 0.f, ss1 = 0.f;
    for (int jj = lane; jj < deg; jj += 32) {
        int s = g_csr[start + jj];
        float2 av = ((const float2*)g_als)[s];
        float e0 = __expf(lrelu(av.x + aldv.x));
        float e1 = __expf(lrelu(av.y + aldv.y));
        ss0 += e0; ss1 += e1;
        s_s[widx][jj] = s;
        ((float2*)s_a[widx])[jj] = make_float2(e0, e1);
    }
#pragma unroll
    for (int o = 16; o > 0; o >>= 1) {
        ss0 += __shfl_xor_sync(0xffffffffu, ss0, o);
        ss1 += __shfl_xor_sync(0xffffffffu, ss1, o);
    }
    __syncwarp();

    // phase C: 4 edge groups x 8 float4 channel-quads; 16-edge chunks
    // => 4 independent LDG.128 in flight per lane per chunk (deep MLP)
    const float4* h4 = (const float4*)g_h;
    int eg = lane >> 3;        // edge group 0..3
    int c4 = lane & 7;         // float4 index -> channels 4c4..4c4+3
    int hsel = c4 >> 2;        // head of this quad
    float ax = 0.f, ay = 0.f, az = 0.f, aw = 0.f;
    int base = 0;
    for (; base + 16 <= deg; base += 16) {
        int   sreg[4];
        float areg[4];
#pragma unroll
        for (int u = 0; u < 4; u++) {
            int e = base + 4 * u + eg;
            sreg[u] = s_s[widx][e];
            areg[u] = s_a[widx][e * 2 + hsel];
        }
        float4 f0 = h4[sreg[0] * 8 + c4];
        float4 f1 = h4[sreg[1] * 8 + c4];
        float4 f2 = h4[sreg[2] * 8 + c4];
        float4 f3 = h4[sreg[3] * 8 + c4];
        ax = fmaf(areg[0], f0.x, ax); ay = fmaf(areg[0], f0.y, ay);
        az = fmaf(areg[0], f0.z, az); aw = fmaf(areg[0], f0.w, aw);
        ax = fmaf(areg[1], f1.x, ax); ay = fmaf(areg[1], f1.y, ay);
        az = fmaf(areg[1], f1.z, az); aw = fmaf(areg[1], f1.w, aw);
        ax = fmaf(areg[2], f2.x, ax); ay = fmaf(areg[2], f2.y, ay);
        az = fmaf(areg[2], f2.z, az); aw = fmaf(areg[2], f2.w, aw);
        ax = fmaf(areg[3], f3.x, ax); ay = fmaf(areg[3], f3.y, ay);
        az = fmaf(areg[3], f3.z, az); aw = fmaf(areg[3], f3.w, aw);
    }
    if (base + 8 <= deg) {
        int e0 = base + eg, e1 = base + 4 + eg;
        int s0 = s_s[widx][e0], s1 = s_s[widx][e1];
        float a0 = s_a[widx][e0 * 2 + hsel];
        float a1 = s_a[widx][e1 * 2 + hsel];
        float4 f0 = h4[s0 * 8 + c4];
        float4 f1 = h4[s1 * 8 + c4];
        ax = fmaf(a0, f0.x, ax); ay = fmaf(a0, f0.y, ay);
        az = fmaf(a0, f0.z, az); aw = fmaf(a0, f0.w, aw);
        ax = fmaf(a1, f1.x, ax); ay = fmaf(a1, f1.y, ay);
        az = fmaf(a1, f1.z, az); aw = fmaf(a1, f1.w, aw);
        base += 8;
    }
#pragma unroll 1
    for (int e = base + eg; e < deg; e += 4) {
        int s = s_s[widx][e];
        float a = s_a[widx][e * 2 + hsel];
        float4 f = h4[s * 8 + c4];
        ax = fmaf(a, f.x, ax); ay = fmaf(a, f.y, ay);
        az = fmaf(a, f.z, az); aw = fmaf(a, f.w, aw);
    }
    // reduce across the 4 edge groups (lane bits 3,4)
#pragma unroll
    for (int o = 8; o <= 16; o <<= 1) {
        ax += __shfl_xor_sync(0xffffffffu, ax, o);
        ay += __shfl_xor_sync(0xffffffffu, ay, o);
        az += __shfl_xor_sync(0xffffffffu, az, o);
        aw += __shfl_xor_sync(0xffffffffu, aw, o);
    }
    float inv = 1.f / ((hsel ? ss1 : ss0) + 1e-16f);
    if (eg == 0)
        ((float4*)g_o)[w * 8 + c4] = make_float4(ax * inv, ay * inv, az * inv, aw * inv);
}

// ---------------- layer 3 edges (H=1, CH=8) fused with output head ----------------
__global__ void __launch_bounds__(256) k_edge1_final(
        const float* __restrict__ b3, const float* __restrict__ Wo,
        const float* __restrict__ bo, float* __restrict__ out) {
    __shared__ int   s_s[NW][SMAX];
    __shared__ float s_a[NW][SMAX];
    int widx = threadIdx.x >> 5;
    int lane = threadIdx.x & 31;
    int w = blockIdx.x * NW + widx;

    int start = w * CAP;
    int deg   = min(g_cnt[w], CAP);
    float aldv = g_ald[w];

    float ss = 0.f;
    for (int jj = lane; jj < deg; jj += 32) {
        int s = g_csr[start + jj];
        float e = __expf(lrelu(g_als[s] + aldv));
        ss += e;
        s_s[widx][jj] = s; s_a[widx][jj] = e;
    }
#pragma unroll
    for (int o = 16; o > 0; o >>= 1) ss += __shfl_xor_sync(0xffffffffu, ss, o);
    __syncwarp();
    float inv = 1.f / (ss + 1e-16f);

    // phase C: 16 edge groups x 2 float4 channel-quads (CH=8 -> 2 x float4 per node)
    const float4* h4 = (const float4*)g_h;
    int eg = lane >> 1;        // 0..15
    int c4 = lane & 1;         // 0..1 -> channels 4c4..4c4+3
    float ax = 0.f, ay = 0.f, az = 0.f, aw = 0.f;
    int base = 0;
    for (; base + 32 <= deg; base += 32) {
        int   s0 = s_s[widx][base + eg],      s1 = s_s[widx][base + 16 + eg];
        float a0 = s_a[widx][base + eg],      a1 = s_a[widx][base + 16 + eg];
        float4 f0 = h4[s0 * 2 + c4];
        float4 f1 = h4[s1 * 2 + c4];
        ax = fmaf(a0, f0.x, ax); ay = fmaf(a0, f0.y, ay);
        az = fmaf(a0, f0.z, az); aw = fmaf(a0, f0.w, aw);
        ax = fmaf(a1, f1.x, ax); ay = fmaf(a1, f1.y, ay);
        az = fmaf(a1, f1.z, az); aw = fmaf(a1, f1.w, aw);
    }
#pragma unroll 1
    for (int e = base + eg; e < deg; e += 16) {
        float a = s_a[widx][e];
        float4 f = h4[s_s[widx][e] * 2 + c4];
        ax = fmaf(a, f.x, ax); ay = fmaf(a, f.y, ay);
        az = fmaf(a, f.z, az); aw = fmaf(a, f.w, aw);
    }
    // reduce over the 16 edge groups (lane bits 1..4)
#pragma unroll
    for (int o = 2; o <= 16; o <<= 1) {
        ax += __shfl_xor_sync(0xffffffffu, ax, o);
        ay += __shfl_xor_sync(0xffffffffu, ay, o);
        az += __shfl_xor_sync(0xffffffffu, az, o);
        aw += __shfl_xor_sync(0xffffffffu, aw, o);
    }

    // fused head on lanes 0 (ch 0-3) and 1 (ch 4-7): y = elu(out3+b3) @ Wo + bo
    float z0 = ax * inv + __ldg(&b3[4 * c4 + 0]);
    float z1 = ay * inv + __ldg(&b3[4 * c4 + 1]);
    float z2 = az * inv + __ldg(&b3[4 * c4 + 2]);
    float z3 = aw * inv + __ldg(&b3[4 * c4 + 3]);
    z0 = z0 > 0.f ? z0 : expm1f(z0);
    z1 = z1 > 0.f ? z1 : expm1f(z1);
    z2 = z2 > 0.f ? z2 : expm1f(z2);
    z3 = z3 > 0.f ? z3 : expm1f(z3);
    float p = fmaf(z0, __ldg(&Wo[4 * c4 + 0]),
             fmaf(z1, __ldg(&Wo[4 * c4 + 1]),
             fmaf(z2, __ldg(&Wo[4 * c4 + 2]), z3 * __ldg(&Wo[4 * c4 + 3]))));
    p += __shfl_xor_sync(0xffffffffu, p, 1);
    if (lane == 0) out[w] = p + __ldg(&bo[0]);
}

// ---------------- mid node transform (quad-wise, low reg pressure) ----------------
template <int CIN, int COUT, int H>
__global__ void __launch_bounds__(256) k_mid(
        const float* __restrict__ b, const float* __restrict__ W,
        const float* __restrict__ as_, const float* __restrict__ ad_) {
    __shared__ float sW[CIN * COUT];
    __shared__ float sb[CIN];
    __shared__ float sas[COUT], sad[COUT];
    for (int i = threadIdx.x; i < CIN * COUT; i += blockDim.x) sW[i] = W[i];
    for (int i = threadIdx.x; i < CIN; i += blockDim.x) sb[i] = b[i];
    for (int i = threadIdx.x; i < COUT; i += blockDim.x) { sas[i] = as_[i]; sad[i] = ad_[i]; }
    __syncthreads();

    int n = blockIdx.x * blockDim.x + threadIdx.x;
    if (n >= NN) return;
    float z[CIN];
#pragma unroll
    for (int j = 0; j < CIN / 4; j++) {
        float4 v4 = ((const float4*)g_o)[n * (CIN / 4) + j];
        float v;
        v = v4.x + sb[4*j+0]; z[4*j+0] = v > 0.f ? v : expm1f(v);
        v = v4.y + sb[4*j+1]; z[4*j+1] = v > 0.f ? v : expm1f(v);
        v = v4.z + sb[4*j+2]; z[4*j+2] = v > 0.f ? v : expm1f(v);
        v = v4.w + sb[4*j+3]; z[4*j+3] = v > 0.f ? v : expm1f(v);
    }
    const int C = COUT / H;
    float als[H], ald[H];
#pragma unroll
    for (int h = 0; h < H; h++) { als[h] = 0.f; ald[h] = 0.f; }
    // quad-wise: 4 accumulators live at a time, store immediately
#pragma unroll
    for (int j = 0; j < COUT / 4; j++) {
        float a0 = 0.f, a1 = 0.f, a2 = 0.f, a3 = 0.f;
        int c0 = 4 * j;
#pragma unroll
        for (int i = 0; i < CIN; i++) {
            float zi = z[i];
            const float* wr = &sW[i * COUT + c0];
            a0 = fmaf(zi, wr[0], a0);
            a1 = fmaf(zi, wr[1], a1);
            a2 = fmaf(zi, wr[2], a2);
            a3 = fmaf(zi, wr[3], a3);
        }
        ((float4*)g_h)[n * (COUT / 4) + j] = make_float4(a0, a1, a2, a3);
        int h = c0 / C;   // quads never straddle heads
        als[h] = fmaf(a0, sas[c0+0], fmaf(a1, sas[c0+1], fmaf(a2, sas[c0+2], fmaf(a3, sas[c0+3], als[h]))));
        ald[h] = fmaf(a0, sad[c0+0], fmaf(a1, sad[c0+1], fmaf(a2, sad[c0+2], fmaf(a3, sad[c0+3], ald[h]))));
    }
#pragma unroll
    for (int h = 0; h < H; h++) { g_als[n * H + h] = als[h]; g_ald[n * H + h] = ald[h]; }
}

// ---------------- launch ----------------
extern "C" void kernel_launch(void* const* d_in, const int* in_sizes, int n_in,
                              void* d_out, int out_size) {
    const float* x   = (const float*)d_in[0];
    const int*   ei  = (const int*)d_in[1];
    const float* W1  = (const float*)d_in[2];
    const float* as1 = (const float*)d_in[3];
    const float* ad1 = (const float*)d_in[4];
    const float* b1  = (const float*)d_in[5];
    const float* W2  = (const float*)d_in[6];
    const float* as2 = (const float*)d_in[7];
    const float* ad2 = (const float*)d_in[8];
    const float* b2  = (const float*)d_in[9];
    const float* W3  = (const float*)d_in[10];
    const float* as3 = (const float*)d_in[11];
    const float* ad3 = (const float*)d_in[12];
    const float* b3  = (const float*)d_in[13];
    const float* Wo  = (const float*)d_in[14];
    const float* bo  = (const float*)d_in[15];
    float* out = (float*)d_out;

    const int4* src4 = (const int4*)ei;            // edge_index[0]
    const int4* dst4 = (const int4*)(ei + NE);     // edge_index[1]

    // node transform first: seeds cursors (g_cnt=1) + self-loop slot 0
    k_node1<<<(NN + 255) / 256, 256>>>(x, W1, as1, ad1);
    // single-pass bucketed adjacency build
    k_scatter<<<(NE / 4 + 255) / 256, 256>>>(src4, dst4);

    const int EB = NN / NW;   // 12500 blocks, one warp per dst node
    // layer 1 edges (H=2, C=16)
    k_edge2<<<EB, 256>>>();
    // layer 2 (H=2, C=16)
    k_mid<32, 32, 2><<<(NN + 255) / 256, 256>>>(b1, W2, as2, ad2);
    k_edge2<<<EB, 256>>>();
    // layer 3 (H=1, C=8) + fused output head
    k_mid<32, 8, 1><<<(NN + 255) / 256, 256>>>(b2, W3, as3, ad3);
    k_edge1_final<<<EB, 256>>>(b3, Wo, bo, out);

    (void)in_sizes; (void)n_in; (void)out_size;
}